// round 4
// baseline (speedup 1.0000x reference)
#include <cuda_runtime.h>
#include <cuda_bf16.h>
#include <cstdint>

// SimpleLSS: softmax over depth sums to 1 -> weighted == img_feat.
// Whole op == bilinear upsample (24,256,16,44) -> (24,256,128,128).
//
// R4: stage output in smem, drain with cp.async.bulk (TMA bulk store).
// Removes all STG wavefronts from the L1tex pipe; TMA moves smem->L2
// directly. Two 32KB chunks overlap compute with drain.

#define IN_H 16
#define IN_W 44
#define OUT_HW 128
#define PLANE_IN (IN_H * IN_W)       // 704
#define PLANE_OUT (OUT_HW * OUT_HW)  // 16384
#define SMEM_BYTES ((2048 + 16384) * 4)  // hrow + outbuf = 73728 B

__device__ __forceinline__ uint32_t smem_u32(const void* p) {
    uint32_t a;
    asm("{ .reg .u64 t; cvta.to.shared.u64 t, %1; cvt.u32.u64 %0, t; }"
        : "=r"(a) : "l"(p));
    return a;
}

__global__ __launch_bounds__(256) void lss_resize_kernel(
    const float* __restrict__ img, float* __restrict__ out)
{
    extern __shared__ float smem[];
    float* hrow   = smem;          // 2048 floats (16 rows x 128)
    float* outbuf = smem + 2048;   // 16384 floats (full output plane)
    float* tile   = outbuf;        // alias: raw input, consumed in stage 1

    const int plane = blockIdx.x;  // n*256 + c
    const float* __restrict__ src = img + (long long)plane * PLANE_IN;
    float* __restrict__ dst = out + (long long)plane * PLANE_OUT;

    // ---- stage 0: load input plane (704 floats) ----
    for (int i = threadIdx.x; i < PLANE_IN; i += 256)
        tile[i] = src[i];
    __syncthreads();

    // ---- stage 1: horizontal interp -> hrow (2048 values, 8/thread) ----
    #pragma unroll
    for (int k = 0; k < 8; ++k) {
        const int i = k * 256 + threadIdx.x;
        const int r = i >> 7;
        const int x = i & 127;
        float sx = fmaxf(((float)x + 0.5f) * 0.34375f - 0.5f, 0.0f);
        int   x0 = (int)sx;
        float fx = sx - (float)x0;
        int   x1 = min(x0 + 1, IN_W - 1);
        const float* rp = tile + r * IN_W;
        float v0 = rp[x0];
        hrow[i] = v0 + fx * (rp[x1] - v0);
    }
    __syncthreads();

    // ---- stage 2: vertical blend into outbuf; drain via TMA per half ----
    #pragma unroll
    for (int half = 0; half < 2; ++half) {
        #pragma unroll
        for (int it = 0; it < 8; ++it) {
            const int l = (half * 8 + it) * 1024 + threadIdx.x * 4;
            const int y = l >> 7;
            const int x = l & 127;
            float sy = fmaxf(((float)y + 0.5f) * 0.125f - 0.5f, 0.0f);
            int   y0 = (int)sy;
            float fy = sy - (float)y0;
            int   y1 = min(y0 + 1, IN_H - 1);
            float4 a = *reinterpret_cast<const float4*>(hrow + y0 * OUT_HW + x);
            float4 b = *reinterpret_cast<const float4*>(hrow + y1 * OUT_HW + x);
            float4 v;
            v.x = a.x + fy * (b.x - a.x);
            v.y = a.y + fy * (b.y - a.y);
            v.z = a.z + fy * (b.z - a.z);
            v.w = a.w + fy * (b.w - a.w);
            *reinterpret_cast<float4*>(outbuf + l) = v;
        }
        // make STS visible to the async proxy, then elect one thread to drain
        asm volatile("fence.proxy.async.shared::cta;" ::: "memory");
        __syncthreads();
        if (threadIdx.x == 0) {
            uint32_t s = smem_u32(outbuf + half * 8192);
            asm volatile(
                "cp.async.bulk.global.shared::cta.bulk_group [%0], [%1], %2;"
                :: "l"(dst + half * 8192), "r"(s), "r"(32768) : "memory");
            asm volatile("cp.async.bulk.commit_group;" ::: "memory");
        }
    }
    // issuing thread waits for TMA reads of smem before CTA teardown
    if (threadIdx.x == 0)
        asm volatile("cp.async.bulk.wait_group.read 0;" ::: "memory");
}

extern "C" void kernel_launch(void* const* d_in, const int* in_sizes, int n_in,
                              void* d_out, int out_size)
{
    const float* img = (const float*)d_in[0];   // (24,256,16,44)
    float* out = (float*)d_out;                 // (24,256,128,128)
    const int planes = in_sizes[0] / PLANE_IN;  // 6144

    cudaFuncSetAttribute(lss_resize_kernel,
                         cudaFuncAttributeMaxDynamicSharedMemorySize,
                         SMEM_BYTES);
    lss_resize_kernel<<<planes, 256, SMEM_BYTES>>>(img, out);
}

// round 5
// speedup vs baseline: 1.3622x; 1.3622x over previous
#include <cuda_runtime.h>
#include <cuda_bf16.h>

// SimpleLSS: softmax over depth sums to 1 -> weighted == img_feat.
// Whole op == bilinear upsample (24,256,16,44) -> (24,256,128,128).
//
// R5: back to direct-STG dataflow (R4's TMA staging lost 2.7x occupancy).
// 128-thread CTAs, one vertical half-plane each (grid=12288): 16 CTAs/SM,
// finer tail granularity, denser store stream. Each CTA loads only the
// 9 input rows it needs; stage-1 horizontal coeffs computed once per thread.

#define IN_H 16
#define IN_W 44
#define OUT_HW 128
#define PLANE_IN (IN_H * IN_W)       // 704
#define PLANE_OUT (OUT_HW * OUT_HW)  // 16384

__global__ __launch_bounds__(128, 16) void lss_resize_kernel(
    const float* __restrict__ img, float* __restrict__ out)
{
    const int bid   = blockIdx.x;
    const int plane = bid >> 1;        // n*256 + c
    const int half  = bid & 1;         // 0: rows 0-63, 1: rows 64-127
    const int t     = threadIdx.x;     // 0..127

    const float* __restrict__ src = img + (long long)plane * PLANE_IN;
    float* __restrict__ dst = out + (long long)plane * PLANE_OUT;

    __shared__ float tile[9 * IN_W];        // 9 input rows (396 floats)
    __shared__ float hrow[IN_H * OUT_HW];   // indexed by global row; 9 used

    // rows needed: half 0 -> hrow 0..8, half 1 -> hrow 7..15
    const int r_base = 7 * half;

    // ---- stage 0: load the 9 input rows this half needs ----
    const float* src2 = src + r_base * IN_W;
    #pragma unroll
    for (int i = t; i < 9 * IN_W; i += 128)
        tile[i] = src2[i];
    __syncthreads();

    // ---- stage 1: horizontal interp, col x = t, 9 rows ----
    {
        // horizontal scale 44/128 = 0.34375 (exact fp32)
        float sx = fmaxf(((float)t + 0.5f) * 0.34375f - 0.5f, 0.0f);
        int   x0 = (int)sx;
        float fx = sx - (float)x0;
        int   x1 = min(x0 + 1, IN_W - 1);
        #pragma unroll
        for (int k = 0; k < 9; ++k) {
            float v0 = tile[k * IN_W + x0];
            float v1 = tile[k * IN_W + x1];
            hrow[(r_base + k) * OUT_HW + t] = v0 + fx * (v1 - v0);
        }
    }
    __syncthreads();

    // ---- stage 2: vertical blend; warp w -> 16 rows, lane c -> cols 4c..4c+3
    const int c = t & 31;
    const int w = t >> 5;
    const int x = c * 4;
    const int y_base = 64 * half + 16 * w;

    #pragma unroll
    for (int r = 0; r < 16; ++r) {
        const int y = y_base + r;
        // vertical scale 16/128 = 0.125
        float sy = fmaxf(((float)y + 0.5f) * 0.125f - 0.5f, 0.0f);
        int   y0 = (int)sy;
        float fy = sy - (float)y0;
        int   y1 = min(y0 + 1, IN_H - 1);
        float4 a = *reinterpret_cast<const float4*>(hrow + y0 * OUT_HW + x);
        float4 b = *reinterpret_cast<const float4*>(hrow + y1 * OUT_HW + x);
        float4 v;
        v.x = a.x + fy * (b.x - a.x);
        v.y = a.y + fy * (b.y - a.y);
        v.z = a.z + fy * (b.z - a.z);
        v.w = a.w + fy * (b.w - a.w);
        __stcs(reinterpret_cast<float4*>(dst + y * OUT_HW + x), v);
    }
}

extern "C" void kernel_launch(void* const* d_in, const int* in_sizes, int n_in,
                              void* d_out, int out_size)
{
    const float* img = (const float*)d_in[0];   // (24,256,16,44)
    float* out = (float*)d_out;                 // (24,256,128,128)
    const int planes = in_sizes[0] / PLANE_IN;  // 6144
    lss_resize_kernel<<<planes * 2, 128>>>(img, out);
}